// round 1
// baseline (speedup 1.0000x reference)
#include <cuda_runtime.h>
#include <math.h>

// LSTM cell: B=8192, I=H=1024.
// pre_g = x @ Wg_i^T + bg_i + h @ Wg_h^T + bg_h   for g in {f,i,g,o}
// ct = sig(pre_f)*c + sig(pre_i)*tanh(pre_g)
// ht = sig(pre_o)*tanh(ct)
// out = [ht (8192*1024) | ct (8192*1024)]
//
// Round 1: fused SIMT fp32 GEMM baseline. Block computes a 64(batch) x 64(hidden)
// tile for ALL 4 gates simultaneously (A tile shared across the 4 weight tiles).
// 256 threads, 4x4 per-thread microtile per gate, K=2048 in chunks of 16 with
// global->register prefetch. Epilogue fused in-register.

#define BATCH 8192
#define IDIM  1024
#define HDIM  1024
#define KSUM  2048   // I + H

#define BM 64
#define BN 64
#define KT 16
#define TM 4
#define TN 4
#define SROW (BM + 4)   // padded row stride (floats); 68*4B = multiple of 16B

__device__ __forceinline__ float sigf(float v) {
    return 1.0f / (1.0f + __expf(-v));
}

__global__ void __launch_bounds__(256, 2)
lstm_fused_kernel(const float* __restrict__ x, const float* __restrict__ h,
                  const float* __restrict__ c,
                  const float* __restrict__ wf_i, const float* __restrict__ bf_i,
                  const float* __restrict__ wf_h, const float* __restrict__ bf_h,
                  const float* __restrict__ wi_i, const float* __restrict__ bi_i,
                  const float* __restrict__ wi_h, const float* __restrict__ bi_h,
                  const float* __restrict__ wg_i, const float* __restrict__ bg_i,
                  const float* __restrict__ wg_h, const float* __restrict__ bg_h,
                  const float* __restrict__ wo_i, const float* __restrict__ bo_i,
                  const float* __restrict__ wo_h, const float* __restrict__ bo_h,
                  float* __restrict__ out)
{
    __shared__ __align__(16) float As[KT][SROW];
    __shared__ __align__(16) float Bs[4][KT][SROW];

    const int tid = threadIdx.x;
    const int tx = tid & 15;         // 0..15  -> hidden cols
    const int ty = tid >> 4;         // 0..15  -> batch rows
    const int mblk = blockIdx.y * BM;
    const int nblk = blockIdx.x * BN;

    const int lrow = tid >> 2;        // 0..63 : tile row loaded by this thread
    const int lkq  = (tid & 3) * 4;   // 0,4,8,12 : k offset within chunk

    const float* wi_tab[4] = {wf_i, wi_i, wg_i, wo_i};
    const float* wh_tab[4] = {wf_h, wi_h, wg_h, wo_h};

    float acc[4][TM][TN];
#pragma unroll
    for (int g = 0; g < 4; g++)
#pragma unroll
        for (int i = 0; i < TM; i++)
#pragma unroll
            for (int j = 0; j < TN; j++) acc[g][i][j] = 0.0f;

    // ---- prefetch first tile (kt = 0, entirely in the x / w*_i half) ----
    float4 aReg, bReg[4];
    {
        const int k = lkq;  // < 1024
        aReg = *reinterpret_cast<const float4*>(&x[(size_t)(mblk + lrow) * IDIM + k]);
#pragma unroll
        for (int g = 0; g < 4; g++)
            bReg[g] = *reinterpret_cast<const float4*>(&wi_tab[g][(size_t)(nblk + lrow) * IDIM + k]);
    }

    for (int kt = 0; kt < KSUM; kt += KT) {
        // ---- commit prefetched regs to shared (transposed: [k][row]) ----
        As[lkq + 0][lrow] = aReg.x;
        As[lkq + 1][lrow] = aReg.y;
        As[lkq + 2][lrow] = aReg.z;
        As[lkq + 3][lrow] = aReg.w;
#pragma unroll
        for (int g = 0; g < 4; g++) {
            Bs[g][lkq + 0][lrow] = bReg[g].x;
            Bs[g][lkq + 1][lrow] = bReg[g].y;
            Bs[g][lkq + 2][lrow] = bReg[g].z;
            Bs[g][lkq + 3][lrow] = bReg[g].w;
        }
        __syncthreads();

        // ---- prefetch next tile while computing this one ----
        const int ktn = kt + KT;
        if (ktn < KSUM) {
            const int k = ktn + lkq;
            if (k < IDIM) {
                aReg = *reinterpret_cast<const float4*>(&x[(size_t)(mblk + lrow) * IDIM + k]);
#pragma unroll
                for (int g = 0; g < 4; g++)
                    bReg[g] = *reinterpret_cast<const float4*>(&wi_tab[g][(size_t)(nblk + lrow) * IDIM + k]);
            } else {
                const int kh = k - IDIM;
                aReg = *reinterpret_cast<const float4*>(&h[(size_t)(mblk + lrow) * HDIM + kh]);
#pragma unroll
                for (int g = 0; g < 4; g++)
                    bReg[g] = *reinterpret_cast<const float4*>(&wh_tab[g][(size_t)(nblk + lrow) * HDIM + kh]);
            }
        }

        // ---- compute on shared tile ----
#pragma unroll
        for (int kk = 0; kk < KT; kk++) {
            float4 a4 = *reinterpret_cast<const float4*>(&As[kk][ty * TM]);
            float a[TM] = {a4.x, a4.y, a4.z, a4.w};
#pragma unroll
            for (int g = 0; g < 4; g++) {
                float4 b4 = *reinterpret_cast<const float4*>(&Bs[g][kk][tx * TN]);
                float b[TN] = {b4.x, b4.y, b4.z, b4.w};
#pragma unroll
                for (int i = 0; i < TM; i++)
#pragma unroll
                    for (int j = 0; j < TN; j++)
                        acc[g][i][j] = fmaf(a[i], b[j], acc[g][i][j]);
            }
        }
        __syncthreads();
    }

    // ---- fused LSTM epilogue ----
    const int n0 = nblk + tx * TN;
    float bsum[4][TN];
#pragma unroll
    for (int j = 0; j < TN; j++) {
        const int n = n0 + j;
        bsum[0][j] = bf_i[n] + bf_h[n];
        bsum[1][j] = bi_i[n] + bi_h[n];
        bsum[2][j] = bg_i[n] + bg_h[n];
        bsum[3][j] = bo_i[n] + bo_h[n];
    }

    float* outH = out;                                  // ht plane
    float* outC = out + (size_t)BATCH * HDIM;           // ct plane

#pragma unroll
    for (int i = 0; i < TM; i++) {
        const int m = mblk + ty * TM + i;
        const size_t base = (size_t)m * HDIM + n0;
        float4 c4 = *reinterpret_cast<const float4*>(&c[base]);
        float cold[TN] = {c4.x, c4.y, c4.z, c4.w};
        float hout[TN], cout[TN];
#pragma unroll
        for (int j = 0; j < TN; j++) {
            float pf = acc[0][i][j] + bsum[0][j];
            float pi = acc[1][i][j] + bsum[1][j];
            float pg = acc[2][i][j] + bsum[2][j];
            float po = acc[3][i][j] + bsum[3][j];
            float ft = sigf(pf);
            float it = sigf(pi);
            float gt = tanhf(pg);
            float ot = sigf(po);
            float cn = fmaf(ft, cold[j], it * gt);
            cout[j] = cn;
            hout[j] = ot * tanhf(cn);
        }
        float4 h4 = make_float4(hout[0], hout[1], hout[2], hout[3]);
        float4 cn4 = make_float4(cout[0], cout[1], cout[2], cout[3]);
        *reinterpret_cast<float4*>(&outH[base]) = h4;
        *reinterpret_cast<float4*>(&outC[base]) = cn4;
    }
}

extern "C" void kernel_launch(void* const* d_in, const int* in_sizes, int n_in,
                              void* d_out, int out_size)
{
    const float* x    = (const float*)d_in[0];
    const float* h    = (const float*)d_in[1];
    const float* c    = (const float*)d_in[2];
    const float* wf_i = (const float*)d_in[3];
    const float* bf_i = (const float*)d_in[4];
    const float* wf_h = (const float*)d_in[5];
    const float* bf_h = (const float*)d_in[6];
    const float* wi_i = (const float*)d_in[7];
    const float* bi_i = (const float*)d_in[8];
    const float* wi_h = (const float*)d_in[9];
    const float* bi_h = (const float*)d_in[10];
    const float* wg_i = (const float*)d_in[11];
    const float* bg_i = (const float*)d_in[12];
    const float* wg_h = (const float*)d_in[13];
    const float* bg_h = (const float*)d_in[14];
    const float* wo_i = (const float*)d_in[15];
    const float* bo_i = (const float*)d_in[16];
    const float* wo_h = (const float*)d_in[17];
    const float* bo_h = (const float*)d_in[18];
    float* out = (float*)d_out;

    dim3 grid(HDIM / BN, BATCH / BM);   // (16, 128)
    dim3 block(256);
    lstm_fused_kernel<<<grid, block>>>(x, h, c,
                                       wf_i, bf_i, wf_h, bf_h,
                                       wi_i, bi_i, wi_h, bi_h,
                                       wg_i, bg_i, wg_h, bg_h,
                                       wo_i, bo_i, wo_h, bo_h,
                                       out);
}

// round 3
// speedup vs baseline: 2.6975x; 2.6975x over previous
#include <cuda_runtime.h>
#include <cstdint>
#include <math.h>

// LSTM cell B=8192, I=H=1024 via mma.sync.m16n8k8 tf32 (compute_103-safe).
// Block: 128(M) x 32(hidden) x 4 gates. 8 warps = 4(M) x 2(N).
// Warp tile 32x16 per gate -> 2x2 m16n8 frags x 4 gates = 64 accums/thread.
// K=2048 in 64 double-buffered stages of 32, global->reg prefetch,
// cvt.rna.tf32 applied once at the smem staging store. Fused LSTM epilogue.

#define BATCH 8192
#define HDIM  1024
#define KT    32
#define NSTAGE 64
#define BM 128
#define BNH 32
#define KPAD 36

#define A_WORDS (BM * KPAD)        // 4608
#define B_WORDS (4 * BNH * KPAD)   // 4608
#define OFF_A(buf) ((buf) * A_WORDS)
#define OFF_B(buf) (2 * A_WORDS + (buf) * B_WORDS)
#define OFF_BIAS   (2 * A_WORDS + 2 * B_WORDS)
#define SMEM_BYTES ((OFF_BIAS + 128) * 4)

__device__ __forceinline__ float sigf(float v) { return 1.0f / (1.0f + __expf(-v)); }

__device__ __forceinline__ uint4 cvt4_tf32(float4 v) {
    uint4 u;
    asm("cvt.rna.tf32.f32 %0, %1;" : "=r"(u.x) : "f"(v.x));
    asm("cvt.rna.tf32.f32 %0, %1;" : "=r"(u.y) : "f"(v.y));
    asm("cvt.rna.tf32.f32 %0, %1;" : "=r"(u.z) : "f"(v.z));
    asm("cvt.rna.tf32.f32 %0, %1;" : "=r"(u.w) : "f"(v.w));
    return u;
}

__device__ __forceinline__ void mma8(float* cacc,
                                     uint32_t a0, uint32_t a1, uint32_t a2, uint32_t a3,
                                     uint32_t b0, uint32_t b1) {
    asm volatile("mma.sync.aligned.m16n8k8.row.col.f32.tf32.tf32.f32 "
                 "{%0,%1,%2,%3}, {%4,%5,%6,%7}, {%8,%9}, {%0,%1,%2,%3};"
                 : "+f"(cacc[0]), "+f"(cacc[1]), "+f"(cacc[2]), "+f"(cacc[3])
                 : "r"(a0), "r"(a1), "r"(a2), "r"(a3), "r"(b0), "r"(b1));
}

__global__ void __launch_bounds__(256, 1)
lstm_mma_kernel(const float* __restrict__ x, const float* __restrict__ h,
                const float* __restrict__ c,
                const float* __restrict__ wf_i, const float* __restrict__ bf_i,
                const float* __restrict__ wf_h, const float* __restrict__ bf_h,
                const float* __restrict__ wi_i, const float* __restrict__ bi_i,
                const float* __restrict__ wi_h, const float* __restrict__ bi_h,
                const float* __restrict__ wg_i, const float* __restrict__ bg_i,
                const float* __restrict__ wg_h, const float* __restrict__ bg_h,
                const float* __restrict__ wo_i, const float* __restrict__ bo_i,
                const float* __restrict__ wo_h, const float* __restrict__ bo_h,
                float* __restrict__ out)
{
    extern __shared__ __align__(16) uint32_t smw[];
    const int tid = threadIdx.x;
    const int lid = tid & 31;
    const int wid = tid >> 5;
    const int warpM = wid & 3;
    const int warpN = wid >> 2;
    const int gid = lid >> 2;    // 0..7
    const int tig = lid & 3;     // 0..3
    const int mblk = blockIdx.y * BM;
    const int nblk = blockIdx.x * BNH;

    const float* wi_tab[4] = {wf_i, wi_i, wg_i, wo_i};
    const float* wh_tab[4] = {wf_h, wi_h, wg_h, wo_h};

    // bias sums -> smem: bias_s[g*32 + j]
    if (tid < 128) {
        const float* bi_tab[4] = {bf_i, bi_i, bg_i, bo_i};
        const float* bh_tab[4] = {bf_h, bi_h, bg_h, bo_h};
        const int g = tid >> 5, j = tid & 31;
        ((float*)(smw + OFF_BIAS))[g * 32 + j] = bi_tab[g][nblk + j] + bh_tab[g][nblk + j];
    }

    const int an = tid >> 3;     // 0..31
    const int aq = tid & 7;      // 0..7

    float acc[4][2][2][4];
#pragma unroll
    for (int g = 0; g < 4; g++)
#pragma unroll
        for (int mt = 0; mt < 2; mt++)
#pragma unroll
            for (int nt = 0; nt < 2; nt++)
#pragma unroll
                for (int e = 0; e < 4; e++) acc[g][mt][nt][e] = 0.0f;

    // ---- prefetch stage 0 (x / w*_i half, kk0 = 0) ----
    float4 ar[4], br[4];
#pragma unroll
    for (int i = 0; i < 4; i++) {
        ar[i] = *(const float4*)&x[(size_t)(mblk + an + 32 * i) * 1024 + aq * 4];
        br[i] = *(const float4*)&wi_tab[i][(size_t)(nblk + an) * 1024 + aq * 4];
    }

    for (int s = 0; s < NSTAGE; s++) {
        const int buf = s & 1;
        uint32_t* As = smw + OFF_A(buf);
        uint32_t* Bs = smw + OFF_B(buf);

        // ---- convert to tf32 (RNA) + store staged regs ----
#pragma unroll
        for (int i = 0; i < 4; i++) {
            *(uint4*)&As[(an + 32 * i) * KPAD + aq * 4] = cvt4_tf32(ar[i]);
            *(uint4*)&Bs[(i * 32 + an) * KPAD + aq * 4] = cvt4_tf32(br[i]);
        }
        __syncthreads();

        // ---- prefetch next stage ----
        if (s + 1 < NSTAGE) {
            const int s1 = s + 1;
            const int kk0 = (s1 * KT) & 1023;
            const float* srcA = (s1 < 32) ? x : h;
            const float* const* wt = (s1 < 32) ? wi_tab : wh_tab;
#pragma unroll
            for (int i = 0; i < 4; i++) {
                ar[i] = *(const float4*)&srcA[(size_t)(mblk + an + 32 * i) * 1024 + kk0 + aq * 4];
                br[i] = *(const float4*)&wt[i][(size_t)(nblk + an) * 1024 + kk0 + aq * 4];
            }
        }

        // ---- compute 4 k-steps of 8 ----
#pragma unroll
        for (int ks = 0; ks < 4; ks++) {
            uint32_t a[2][4];
#pragma unroll
            for (int mt = 0; mt < 2; mt++) {
                const int r0 = warpM * 32 + mt * 16 + gid;
                const int w = r0 * KPAD + ks * 8 + tig;
                a[mt][0] = As[w];
                a[mt][1] = As[w + 8 * KPAD];
                a[mt][2] = As[w + 4];
                a[mt][3] = As[w + 4 + 8 * KPAD];
            }
#pragma unroll
            for (int g = 0; g < 4; g++)
#pragma unroll
                for (int nt = 0; nt < 2; nt++) {
                    const int nr = g * 32 + warpN * 16 + nt * 8 + gid;
                    const int w = nr * KPAD + ks * 8 + tig;
                    const uint32_t b0 = Bs[w];
                    const uint32_t b1 = Bs[w + 4];
                    mma8(acc[g][0][nt], a[0][0], a[0][1], a[0][2], a[0][3], b0, b1);
                    mma8(acc[g][1][nt], a[1][0], a[1][1], a[1][2], a[1][3], b0, b1);
                }
        }
        __syncthreads();
    }

    // ---- fused LSTM epilogue ----
    const float* bias_s = (const float*)(smw + OFF_BIAS);
    float* outH = out;
    float* outC = out + (size_t)BATCH * HDIM;

#pragma unroll
    for (int nt = 0; nt < 2; nt++) {
        const int colloc = warpN * 16 + nt * 8 + tig * 2;
        const float bF0 = bias_s[0 * 32 + colloc], bF1 = bias_s[0 * 32 + colloc + 1];
        const float bI0 = bias_s[1 * 32 + colloc], bI1 = bias_s[1 * 32 + colloc + 1];
        const float bG0 = bias_s[2 * 32 + colloc], bG1 = bias_s[2 * 32 + colloc + 1];
        const float bO0 = bias_s[3 * 32 + colloc], bO1 = bias_s[3 * 32 + colloc + 1];
#pragma unroll
        for (int mt = 0; mt < 2; mt++)
#pragma unroll
            for (int p = 0; p < 2; p++) {
                const int m = mblk + warpM * 32 + mt * 16 + gid + 8 * p;
                const size_t base = (size_t)m * HDIM + nblk + colloc;
                const float2 cc = *(const float2*)&c[base];
                const int e = p * 2;
                const float pf0 = acc[0][mt][nt][e] + bF0, pf1 = acc[0][mt][nt][e + 1] + bF1;
                const float pi0 = acc[1][mt][nt][e] + bI0, pi1 = acc[1][mt][nt][e + 1] + bI1;
                const float pg0 = acc[2][mt][nt][e] + bG0, pg1 = acc[2][mt][nt][e + 1] + bG1;
                const float po0 = acc[3][mt][nt][e] + bO0, po1 = acc[3][mt][nt][e + 1] + bO1;
                const float f0 = sigf(pf0), f1 = sigf(pf1);
                const float i0 = sigf(pi0), i1 = sigf(pi1);
                const float g0 = tanhf(pg0), g1 = tanhf(pg1);
                const float o0 = sigf(po0), o1 = sigf(po1);
                const float cn0 = fmaf(f0, cc.x, i0 * g0);
                const float cn1 = fmaf(f1, cc.y, i1 * g1);
                float2 hv = make_float2(o0 * tanhf(cn0), o1 * tanhf(cn1));
                float2 cv = make_float2(cn0, cn1);
                *(float2*)&outH[base] = hv;
                *(float2*)&outC[base] = cv;
            }
    }
}

extern "C" void kernel_launch(void* const* d_in, const int* in_sizes, int n_in,
                              void* d_out, int out_size)
{
    const float* x    = (const float*)d_in[0];
    const float* h    = (const float*)d_in[1];
    const float* c    = (const float*)d_in[2];
    const float* wf_i = (const float*)d_in[3];
    const float* bf_i = (const float*)d_in[4];
    const float* wf_h = (const float*)d_in[5];
    const float* bf_h = (const float*)d_in[6];
    const float* wi_i = (const float*)d_in[7];
    const float* bi_i = (const float*)d_in[8];
    const float* wi_h = (const float*)d_in[9];
    const float* bi_h = (const float*)d_in[10];
    const float* wg_i = (const float*)d_in[11];
    const float* bg_i = (const float*)d_in[12];
    const float* wg_h = (const float*)d_in[13];
    const float* bg_h = (const float*)d_in[14];
    const float* wo_i = (const float*)d_in[15];
    const float* bo_i = (const float*)d_in[16];
    const float* wo_h = (const float*)d_in[17];
    const float* bo_h = (const float*)d_in[18];
    float* out = (float*)d_out;

    cudaFuncSetAttribute(lstm_mma_kernel, cudaFuncAttributeMaxDynamicSharedMemorySize, SMEM_BYTES);

    dim3 grid(HDIM / BNH, BATCH / BM);   // (32, 64)
    lstm_mma_kernel<<<grid, 256, SMEM_BYTES>>>(x, h, c,
                                               wf_i, bf_i, wf_h, bf_h,
                                               wi_i, bi_i, wi_h, bi_h,
                                               wg_i, bg_i, wg_h, bg_h,
                                               wo_i, bo_i, wo_h, bo_h,
                                               out);
}

// round 6
// speedup vs baseline: 2.7040x; 1.0024x over previous
#include <cuda_runtime.h>
#include <cstdint>
#include <math.h>

// LSTM cell B=8192, I=H=1024 via mma.sync.m16n8k8 tf32 (compute_103-safe).
// Block: 128(M) x 32(hidden) x 4 gates. 8 warps = 4(M) x 2(N).
// Warp tile 32x16 per gate -> 2x2 m16n8 frags x 4 gates = 64 accums/thread.
// K=2048 in 64 double-buffered stages of 32, global->reg prefetch,
// cvt.rna.tf32 applied once at the smem staging store. Fused LSTM epilogue.

#define BATCH 8192
#define HDIM  1024
#define KT    32
#define NSTAGE 64
#define BM 128
#define BNH 32
#define KPAD 36

#define A_WORDS (BM * KPAD)        // 4608
#define B_WORDS (4 * BNH * KPAD)   // 4608
#define OFF_A(buf) ((buf) * A_WORDS)
#define OFF_B(buf) (2 * A_WORDS + (buf) * B_WORDS)
#define OFF_BIAS   (2 * A_WORDS + 2 * B_WORDS)
#define SMEM_BYTES ((OFF_BIAS + 128) * 4)

__device__ __forceinline__ float sigf(float v) { return 1.0f / (1.0f + __expf(-v)); }

__device__ __forceinline__ uint4 cvt4_tf32(float4 v) {
    uint4 u;
    asm("cvt.rna.tf32.f32 %0, %1;" : "=r"(u.x) : "f"(v.x));
    asm("cvt.rna.tf32.f32 %0, %1;" : "=r"(u.y) : "f"(v.y));
    asm("cvt.rna.tf32.f32 %0, %1;" : "=r"(u.z) : "f"(v.z));
    asm("cvt.rna.tf32.f32 %0, %1;" : "=r"(u.w) : "f"(v.w));
    return u;
}

__device__ __forceinline__ void mma8(float* cacc,
                                     uint32_t a0, uint32_t a1, uint32_t a2, uint32_t a3,
                                     uint32_t b0, uint32_t b1) {
    asm volatile("mma.sync.aligned.m16n8k8.row.col.f32.tf32.tf32.f32 "
                 "{%0,%1,%2,%3}, {%4,%5,%6,%7}, {%8,%9}, {%0,%1,%2,%3};"
                 : "+f"(cacc[0]), "+f"(cacc[1]), "+f"(cacc[2]), "+f"(cacc[3])
                 : "r"(a0), "r"(a1), "r"(a2), "r"(a3), "r"(b0), "r"(b1));
}

__global__ void __launch_bounds__(256, 1)
lstm_mma_kernel(const float* __restrict__ x, const float* __restrict__ h,
                const float* __restrict__ c,
                const float* __restrict__ wf_i, const float* __restrict__ bf_i,
                const float* __restrict__ wf_h, const float* __restrict__ bf_h,
                const float* __restrict__ wi_i, const float* __restrict__ bi_i,
                const float* __restrict__ wi_h, const float* __restrict__ bi_h,
                const float* __restrict__ wg_i, const float* __restrict__ bg_i,
                const float* __restrict__ wg_h, const float* __restrict__ bg_h,
                const float* __restrict__ wo_i, const float* __restrict__ bo_i,
                const float* __restrict__ wo_h, const float* __restrict__ bo_h,
                float* __restrict__ out)
{
    extern __shared__ __align__(16) uint32_t smw[];
    const int tid = threadIdx.x;
    const int lid = tid & 31;
    const int wid = tid >> 5;
    const int warpM = wid & 3;
    const int warpN = wid >> 2;
    const int gid = lid >> 2;    // 0..7
    const int tig = lid & 3;     // 0..3
    const int mblk = blockIdx.y * BM;
    const int nblk = blockIdx.x * BNH;

    const float* wi_tab[4] = {wf_i, wi_i, wg_i, wo_i};
    const float* wh_tab[4] = {wf_h, wi_h, wg_h, wo_h};

    // bias sums -> smem: bias_s[g*32 + j]
    if (tid < 128) {
        const float* bi_tab[4] = {bf_i, bi_i, bg_i, bo_i};
        const float* bh_tab[4] = {bf_h, bi_h, bg_h, bo_h};
        const int g = tid >> 5, j = tid & 31;
        ((float*)(smw + OFF_BIAS))[g * 32 + j] = bi_tab[g][nblk + j] + bh_tab[g][nblk + j];
    }

    const int an = tid >> 3;     // 0..31
    const int aq = tid & 7;      // 0..7

    float acc[4][2][2][4];
#pragma unroll
    for (int g = 0; g < 4; g++)
#pragma unroll
        for (int mt = 0; mt < 2; mt++)
#pragma unroll
            for (int nt = 0; nt < 2; nt++)
#pragma unroll
                for (int e = 0; e < 4; e++) acc[g][mt][nt][e] = 0.0f;

    // ---- prefetch stage 0 (x / w*_i half, kk0 = 0) ----
    float4 ar[4], br[4];
#pragma unroll
    for (int i = 0; i < 4; i++) {
        ar[i] = *(const float4*)&x[(size_t)(mblk + an + 32 * i) * 1024 + aq * 4];
        br[i] = *(const float4*)&wi_tab[i][(size_t)(nblk + an) * 1024 + aq * 4];
    }

    for (int s = 0; s < NSTAGE; s++) {
        const int buf = s & 1;
        uint32_t* As = smw + OFF_A(buf);
        uint32_t* Bs = smw + OFF_B(buf);

        // ---- convert to tf32 (RNA) + store staged regs ----
#pragma unroll
        for (int i = 0; i < 4; i++) {
            *(uint4*)&As[(an + 32 * i) * KPAD + aq * 4] = cvt4_tf32(ar[i]);
            *(uint4*)&Bs[(i * 32 + an) * KPAD + aq * 4] = cvt4_tf32(br[i]);
        }
        __syncthreads();

        // ---- prefetch next stage ----
        if (s + 1 < NSTAGE) {
            const int s1 = s + 1;
            const int kk0 = (s1 * KT) & 1023;
            const float* srcA = (s1 < 32) ? x : h;
            const float* const* wt = (s1 < 32) ? wi_tab : wh_tab;
#pragma unroll
            for (int i = 0; i < 4; i++) {
                ar[i] = *(const float4*)&srcA[(size_t)(mblk + an + 32 * i) * 1024 + kk0 + aq * 4];
                br[i] = *(const float4*)&wt[i][(size_t)(nblk + an) * 1024 + kk0 + aq * 4];
            }
        }

        // ---- compute 4 k-steps of 8 ----
#pragma unroll
        for (int ks = 0; ks < 4; ks++) {
            uint32_t a[2][4];
#pragma unroll
            for (int mt = 0; mt < 2; mt++) {
                const int r0 = warpM * 32 + mt * 16 + gid;
                const int w = r0 * KPAD + ks * 8 + tig;
                a[mt][0] = As[w];
                a[mt][1] = As[w + 8 * KPAD];
                a[mt][2] = As[w + 4];
                a[mt][3] = As[w + 4 + 8 * KPAD];
            }
#pragma unroll
            for (int g = 0; g < 4; g++)
#pragma unroll
                for (int nt = 0; nt < 2; nt++) {
                    const int nr = g * 32 + warpN * 16 + nt * 8 + gid;
                    const int w = nr * KPAD + ks * 8 + tig;
                    const uint32_t b0 = Bs[w];
                    const uint32_t b1 = Bs[w + 4];
                    mma8(acc[g][0][nt], a[0][0], a[0][1], a[0][2], a[0][3], b0, b1);
                    mma8(acc[g][1][nt], a[1][0], a[1][1], a[1][2], a[1][3], b0, b1);
                }
        }
        __syncthreads();
    }

    // ---- fused LSTM epilogue ----
    const float* bias_s = (const float*)(smw + OFF_BIAS);
    float* outH = out;
    float* outC = out + (size_t)BATCH * HDIM;

#pragma unroll
    for (int nt = 0; nt < 2; nt++) {
        const int colloc = warpN * 16 + nt * 8 + tig * 2;
        const float bF0 = bias_s[0 * 32 + colloc], bF1 = bias_s[0 * 32 + colloc + 1];
        const float bI0 = bias_s[1 * 32 + colloc], bI1 = bias_s[1 * 32 + colloc + 1];
        const float bG0 = bias_s[2 * 32 + colloc], bG1 = bias_s[2 * 32 + colloc + 1];
        const float bO0 = bias_s[3 * 32 + colloc], bO1 = bias_s[3 * 32 + colloc + 1];
#pragma unroll
        for (int mt = 0; mt < 2; mt++)
#pragma unroll
            for (int p = 0; p < 2; p++) {
                const int m = mblk + warpM * 32 + mt * 16 + gid + 8 * p;
                const size_t base = (size_t)m * HDIM + nblk + colloc;
                const float2 cc = *(const float2*)&c[base];
                const int e = p * 2;
                const float pf0 = acc[0][mt][nt][e] + bF0, pf1 = acc[0][mt][nt][e + 1] + bF1;
                const float pi0 = acc[1][mt][nt][e] + bI0, pi1 = acc[1][mt][nt][e + 1] + bI1;
                const float pg0 = acc[2][mt][nt][e] + bG0, pg1 = acc[2][mt][nt][e + 1] + bG1;
                const float po0 = acc[3][mt][nt][e] + bO0, po1 = acc[3][mt][nt][e + 1] + bO1;
                const float f0 = sigf(pf0), f1 = sigf(pf1);
                const float i0 = sigf(pi0), i1 = sigf(pi1);
                const float g0 = tanhf(pg0), g1 = tanhf(pg1);
                const float o0 = sigf(po0), o1 = sigf(po1);
                const float cn0 = fmaf(f0, cc.x, i0 * g0);
                const float cn1 = fmaf(f1, cc.y, i1 * g1);
                float2 hv = make_float2(o0 * tanhf(cn0), o1 * tanhf(cn1));
                float2 cv = make_float2(cn0, cn1);
                *(float2*)&outH[base] = hv;
                *(float2*)&outC[base] = cv;
            }
    }
}

extern "C" void kernel_launch(void* const* d_in, const int* in_sizes, int n_in,
                              void* d_out, int out_size)
{
    const float* x    = (const float*)d_in[0];
    const float* h    = (const float*)d_in[1];
    const float* c    = (const float*)d_in[2];
    const float* wf_i = (const float*)d_in[3];
    const float* bf_i = (const float*)d_in[4];
    const float* wf_h = (const float*)d_in[5];
    const float* bf_h = (const float*)d_in[6];
    const float* wi_i = (const float*)d_in[7];
    const float* bi_i = (const float*)d_in[8];
    const float* wi_h = (const float*)d_in[9];
    const float* bi_h = (const float*)d_in[10];
    const float* wg_i = (const float*)d_in[11];
    const float* bg_i = (const float*)d_in[12];
    const float* wg_h = (const float*)d_in[13];
    const float* bg_h = (const float*)d_in[14];
    const float* wo_i = (const float*)d_in[15];
    const float* bo_i = (const float*)d_in[16];
    const float* wo_h = (const float*)d_in[17];
    const float* bo_h = (const float*)d_in[18];
    float* out = (float*)d_out;

    cudaFuncSetAttribute(lstm_mma_kernel, cudaFuncAttributeMaxDynamicSharedMemorySize, SMEM_BYTES);

    dim3 grid(HDIM / BNH, BATCH / BM);   // (32, 64)
    lstm_mma_kernel<<<grid, 256, SMEM_BYTES>>>(x, h, c,
                                               wf_i, bf_i, wf_h, bf_h,
                                               wi_i, bi_i, wi_h, bi_h,
                                               wg_i, bg_i, wg_h, bg_h,
                                               wo_i, bo_i, wo_h, bo_h,
                                               out);
}

// round 7
// speedup vs baseline: 3.5239x; 1.3032x over previous
#include <cuda_runtime.h>
#include <cstdint>
#include <math.h>

// LSTM cell B=8192, I=H=1024, mma.sync.m16n8k8 tf32.
// Round 7: prepass converts inputs+weights to tf32 (RNA) into __device__
// scratch laid out in exact MMA fragment order; main kernel cp.async 3-stage
// pipeline, LDS.128/LDS.64 fragment loads, 2 CTAs/SM, fused LSTM epilogue.

#define BATCH  8192
#define HDIM   1024
#define NSTAGE 64
#define STAGE_WORDS 8192                    // 32KB per stage (A 16KB + B 16KB)
#define SMEM_WORDS  (3 * STAGE_WORDS + 128)
#define SMEM_BYTES  (SMEM_WORDS * 4)        // 98816

// Fragment-major tf32 scratch.
// gA: [RT=512][kt=256][lane=32][4 words]; word j of lane:
//   j0=(r=16RT+gid,   k=8kt+tig)   j1=(r+8, k)   j2=(r, k+4)   j3=(r+8, k+4)
// gB: [g=4][NT=128][kt=256][lane=32][2 words]; (n=8NT+gid, k=8kt+tig+4j)
__device__ __align__(128) uint32_t gA[16777216];   // 64MB
__device__ __align__(128) uint32_t gB[8388608];    // 32MB

__device__ __forceinline__ uint32_t cvt_tf32(float v) {
    uint32_t u; asm("cvt.rna.tf32.f32 %0, %1;" : "=r"(u) : "f"(v)); return u;
}
__device__ __forceinline__ float sigf(float v) { return 1.0f / (1.0f + __expf(-v)); }

__device__ __forceinline__ uint32_t smem_u32(const void* p) {
    uint32_t a;
    asm("{ .reg .u64 t; cvta.to.shared.u64 t, %1; cvt.u32.u64 %0, t; }" : "=r"(a) : "l"(p));
    return a;
}
__device__ __forceinline__ void cpa16(uint32_t sdst, const void* gsrc) {
    asm volatile("cp.async.cg.shared.global [%0], [%1], 16;" :: "r"(sdst), "l"(gsrc) : "memory");
}
__device__ __forceinline__ void mma8(float* c,
                                     uint32_t a0, uint32_t a1, uint32_t a2, uint32_t a3,
                                     uint32_t b0, uint32_t b1) {
    asm volatile("mma.sync.aligned.m16n8k8.row.col.f32.tf32.tf32.f32 "
                 "{%0,%1,%2,%3}, {%4,%5,%6,%7}, {%8,%9}, {%0,%1,%2,%3};"
                 : "+f"(c[0]), "+f"(c[1]), "+f"(c[2]), "+f"(c[3])
                 : "r"(a0), "r"(a1), "r"(a2), "r"(a3), "r"(b0), "r"(b1));
}

// ---------------- prepass A: x|h -> gA ----------------
__global__ void __launch_bounds__(256)
prepA_kernel(const float* __restrict__ x, const float* __restrict__ h)
{
    const uint32_t cid  = blockIdx.x * 256u + threadIdx.x;  // < 4194304
    const uint32_t lane = cid & 31u;
    const uint32_t kt   = (cid >> 5) & 255u;
    const uint32_t RT   = cid >> 13;
    const uint32_t r0   = RT * 16u + (lane >> 2);
    const uint32_t c0   = kt * 8u + (lane & 3u);            // tig<4 so c0,c0+4 same 1024-half
    const float* s = (c0 < 1024u) ? x : h;
    const uint32_t cc = c0 & 1023u;
    uint4 o;
    o.x = cvt_tf32(s[(size_t)r0 * 1024 + cc]);
    o.y = cvt_tf32(s[(size_t)(r0 + 8) * 1024 + cc]);
    o.z = cvt_tf32(s[(size_t)r0 * 1024 + cc + 4]);
    o.w = cvt_tf32(s[(size_t)(r0 + 8) * 1024 + cc + 4]);
    *reinterpret_cast<uint4*>(&gA[(size_t)cid * 4]) = o;
}

// ---------------- prepass B: 8 weight mats -> gB ----------------
__global__ void __launch_bounds__(256)
prepB_kernel(const float* __restrict__ wf_i, const float* __restrict__ wf_h,
             const float* __restrict__ wi_i, const float* __restrict__ wi_h,
             const float* __restrict__ wg_i, const float* __restrict__ wg_h,
             const float* __restrict__ wo_i, const float* __restrict__ wo_h)
{
    const uint32_t cb = blockIdx.x * 256u + threadIdx.x;    // < 2097152
    const uint32_t cp = cb & 15u;
    const uint32_t tt = cb >> 4;
    const uint32_t kt = tt & 255u;
    const uint32_t nt = (tt >> 8) & 127u;
    const uint32_t g  = tt >> 15;
    const float* wi = (g == 0) ? wf_i : (g == 1) ? wi_i : (g == 2) ? wg_i : wo_i;
    const float* wh = (g == 0) ? wf_h : (g == 1) ? wi_h : (g == 2) ? wg_h : wo_h;
    uint32_t vals[4];
#pragma unroll
    for (int e = 0; e < 2; e++) {
        const uint32_t l = cp * 2u + e;
        const uint32_t n = nt * 8u + (l >> 2);
#pragma unroll
        for (int j = 0; j < 2; j++) {
            const uint32_t k = kt * 8u + (l & 3u) + 4u * j;
            const float* s = (k < 1024u) ? wi : wh;
            vals[e * 2 + j] = cvt_tf32(s[(size_t)n * 1024 + (k & 1023u)]);
        }
    }
    uint4 o = make_uint4(vals[0], vals[1], vals[2], vals[3]);
    *reinterpret_cast<uint4*>(&gB[(size_t)cb * 4]) = o;
}

// ---------------- main kernel ----------------
__global__ void __launch_bounds__(256, 2)
lstm_main(const float* __restrict__ c,
          const float* __restrict__ bf_i, const float* __restrict__ bf_h,
          const float* __restrict__ bi_i, const float* __restrict__ bi_h,
          const float* __restrict__ bg_i, const float* __restrict__ bg_h,
          const float* __restrict__ bo_i, const float* __restrict__ bo_h,
          float* __restrict__ out)
{
    extern __shared__ __align__(16) uint32_t smw[];
    const uint32_t sb = smem_u32(smw);
    const int tid = threadIdx.x;
    const int lid = tid & 31;
    const int wid = tid >> 5;
    const int warpM = wid & 3;
    const int warpN = wid >> 2;
    const int nb = blockIdx.x;     // 0..31 hidden blocks of 32
    const int mb = blockIdx.y;     // 0..63 batch blocks of 128

    // bias sums -> smem tail
    if (tid < 128) {
        const float* bi_tab[4] = {bf_i, bi_i, bg_i, bo_i};
        const float* bh_tab[4] = {bf_h, bi_h, bg_h, bo_h};
        const int g = tid >> 5, j = tid & 31;
        ((float*)(smw + 3 * STAGE_WORDS))[g * 32 + j] =
            bi_tab[g][nb * 32 + j] + bh_tab[g][nb * 32 + j];
    }

    // per-thread cp.async sources/dests (4 A chunks + 4 B chunks of 16B per stage)
    const uint32_t* aSrc[4]; uint32_t aDst[4];
    const uint32_t* bSrc[4]; uint32_t bDst[4];
#pragma unroll
    for (int i = 0; i < 4; i++) {
        const uint32_t ca = (uint32_t)tid * 4u + i;          // 0..1023
        // A: tile t = rtl*4+ksl (0..31), lane16 within tile
        const uint32_t t = ca >> 5, lane16 = ca & 31u;
        const uint32_t rtl = t >> 2, ksl = t & 3u;
        aSrc[i] = gA + (size_t)((((mb * 8u + rtl) * 256u + ksl) * 32u + lane16) * 4u);
        aDst[i] = (t * 128u + lane16 * 4u) * 4u;             // bytes within stage
        // B: tile tt = g*16 + ntl*4 + ksb (0..63), cp = 16B chunk within tile
        const uint32_t tt = ca >> 4, cp = ca & 15u;
        const uint32_t g = tt >> 4, ntl = (tt >> 2) & 3u, ksb = tt & 3u;
        bSrc[i] = gB + (size_t)(((((g * 128u + nb * 4u + ntl) * 256u) + ksb) * 64u + cp * 4u));
        bDst[i] = (4096u + tt * 64u + cp * 4u) * 4u;
    }

#define ISSUE_STAGE(buf_)                                                     \
    do {                                                                      \
        const uint32_t base_ = sb + (uint32_t)(buf_) * 32768u;                \
        _Pragma("unroll")                                                     \
        for (int i_ = 0; i_ < 4; i_++) {                                      \
            cpa16(base_ + aDst[i_], aSrc[i_]); aSrc[i_] += 512;               \
        }                                                                     \
        _Pragma("unroll")                                                     \
        for (int i_ = 0; i_ < 4; i_++) {                                      \
            cpa16(base_ + bDst[i_], bSrc[i_]); bSrc[i_] += 256;               \
        }                                                                     \
        asm volatile("cp.async.commit_group;" ::: "memory");                  \
    } while (0)

    float acc[4][2][2][4];
#pragma unroll
    for (int g = 0; g < 4; g++)
#pragma unroll
        for (int mt = 0; mt < 2; mt++)
#pragma unroll
            for (int nt = 0; nt < 2; nt++)
#pragma unroll
                for (int e = 0; e < 4; e++) acc[g][mt][nt][e] = 0.0f;

    ISSUE_STAGE(0);
    ISSUE_STAGE(1);
    int bufn = 2;

    for (int s = 0; s < NSTAGE; s++) {
        const int bufc = s % 3;
        if (s < NSTAGE - 1) asm volatile("cp.async.wait_group 1;" ::: "memory");
        else                asm volatile("cp.async.wait_group 0;" ::: "memory");
        __syncthreads();

        const uint32_t* Ap = smw + bufc * STAGE_WORDS + warpM * 1024 + lid * 4;
        const uint32_t* Bp = smw + bufc * STAGE_WORDS + 4096 + warpN * 512 + lid * 2;

#pragma unroll
        for (int ks = 0; ks < 4; ks++) {
            const uint4 a0 = *reinterpret_cast<const uint4*>(Ap + ks * 128);
            const uint4 a1 = *reinterpret_cast<const uint4*>(Ap + 512 + ks * 128);
#pragma unroll
            for (int g = 0; g < 4; g++)
#pragma unroll
                for (int nt = 0; nt < 2; nt++) {
                    const uint2 b = *reinterpret_cast<const uint2*>(
                        Bp + g * 1024 + nt * 256 + ks * 64);
                    mma8(acc[g][0][nt], a0.x, a0.y, a0.z, a0.w, b.x, b.y);
                    mma8(acc[g][1][nt], a1.x, a1.y, a1.z, a1.w, b.x, b.y);
                }
        }

        if (s + 2 < NSTAGE) {
            ISSUE_STAGE(bufn);
            bufn = (bufn == 2) ? 0 : bufn + 1;
        }
    }

    // ---- fused LSTM epilogue ----
    const int gid = lid >> 2;
    const int tig = lid & 3;
    const float* bias_s = (const float*)(smw + 3 * STAGE_WORDS);
    float* outH = out;
    float* outC = out + (size_t)BATCH * HDIM;
    const int mblk = mb * 128;
    const int nblk = nb * 32;

#pragma unroll
    for (int nt = 0; nt < 2; nt++) {
        const int colloc = warpN * 16 + nt * 8 + tig * 2;
        const float bF0 = bias_s[0 * 32 + colloc], bF1 = bias_s[0 * 32 + colloc + 1];
        const float bI0 = bias_s[1 * 32 + colloc], bI1 = bias_s[1 * 32 + colloc + 1];
        const float bG0 = bias_s[2 * 32 + colloc], bG1 = bias_s[2 * 32 + colloc + 1];
        const float bO0 = bias_s[3 * 32 + colloc], bO1 = bias_s[3 * 32 + colloc + 1];
#pragma unroll
        for (int mt = 0; mt < 2; mt++)
#pragma unroll
            for (int p = 0; p < 2; p++) {
                const int m = mblk + warpM * 32 + mt * 16 + gid + 8 * p;
                const size_t base = (size_t)m * HDIM + nblk + colloc;
                const float2 cc = *(const float2*)&c[base];
                const int e = p * 2;
                const float pf0 = acc[0][mt][nt][e] + bF0, pf1 = acc[0][mt][nt][e + 1] + bF1;
                const float pi0 = acc[1][mt][nt][e] + bI0, pi1 = acc[1][mt][nt][e + 1] + bI1;
                const float pg0 = acc[2][mt][nt][e] + bG0, pg1 = acc[2][mt][nt][e + 1] + bG1;
                const float po0 = acc[3][mt][nt][e] + bO0, po1 = acc[3][mt][nt][e + 1] + bO1;
                const float f0 = sigf(pf0), f1 = sigf(pf1);
                const float i0 = sigf(pi0), i1 = sigf(pi1);
                const float g0 = tanhf(pg0), g1 = tanhf(pg1);
                const float o0 = sigf(po0), o1 = sigf(po1);
                const float cn0 = fmaf(f0, cc.x, i0 * g0);
                const float cn1 = fmaf(f1, cc.y, i1 * g1);
                *(float2*)&outH[base] = make_float2(o0 * tanhf(cn0), o1 * tanhf(cn1));
                *(float2*)&outC[base] = make_float2(cn0, cn1);
            }
    }
}

extern "C" void kernel_launch(void* const* d_in, const int* in_sizes, int n_in,
                              void* d_out, int out_size)
{
    const float* x    = (const float*)d_in[0];
    const float* h    = (const float*)d_in[1];
    const float* c    = (const float*)d_in[2];
    const float* wf_i = (const float*)d_in[3];
    const float* bf_i = (const float*)d_in[4];
    const float* wf_h = (const float*)d_in[5];
    const float* bf_h = (const float*)d_in[6];
    const float* wi_i = (const float*)d_in[7];
    const float* bi_i = (const float*)d_in[8];
    const float* wi_h = (const float*)d_in[9];
    const float* bi_h = (const float*)d_in[10];
    const float* wg_i = (const float*)d_in[11];
    const float* bg_i = (const float*)d_in[12];
    const float* wg_h = (const float*)d_in[13];
    const float* bg_h = (const float*)d_in[14];
    const float* wo_i = (const float*)d_in[15];
    const float* bo_i = (const float*)d_in[16];
    const float* wo_h = (const float*)d_in[17];
    const float* bo_h = (const float*)d_in[18];
    float* out = (float*)d_out;

    cudaFuncSetAttribute(lstm_main, cudaFuncAttributeMaxDynamicSharedMemorySize, SMEM_BYTES);

    prepA_kernel<<<16384, 256>>>(x, h);
    prepB_kernel<<<8192, 256>>>(wf_i, wf_h, wi_i, wi_h, wg_i, wg_h, wo_i, wo_h);

    dim3 grid(HDIM / 32, BATCH / 128);   // (32, 64)
    lstm_main<<<grid, 256, SMEM_BYTES>>>(c,
                                         bf_i, bf_h, bi_i, bi_h,
                                         bg_i, bg_h, bo_i, bo_h,
                                         out);
}